// round 3
// baseline (speedup 1.0000x reference)
#include <cuda_runtime.h>
#include <math.h>

#define HH 128
#define SS 65
#define SP 68          // padded S (stride), cols 65..67 kept zero
#define NT 512

__device__ __forceinline__ void fma4(float4& acc, float a, const float4& b) {
    acc.x = fmaf(a, b.x, acc.x);
    acc.y = fmaf(a, b.y, acc.y);
    acc.z = fmaf(a, b.z, acc.z);
    acc.w = fmaf(a, b.w, acc.w);
}
// sequential in-order dot: acc += a.x*b.x; then .y, .z, .w (single chain)
__device__ __forceinline__ float dot4(const float4& a, const float4& b, float acc) {
    acc = fmaf(a.x, b.x, acc);
    acc = fmaf(a.y, b.y, acc);
    acc = fmaf(a.z, b.z, acc);
    acc = fmaf(a.w, b.w, acc);
    return acc;
}

// sC[j*SP + t] = sum_k A[j*HH + k] * sB[k*SP + t]
// Each output element: ONE sequential in-order fp32 fma chain over k=0..127.
__device__ __forceinline__ void gemm_gA(const float* __restrict__ A,
                                        const float* __restrict__ sB,
                                        float* __restrict__ sC) {
    for (int tile = threadIdx.x; tile < 32 * 17; tile += NT) {
        int j0 = (tile / 17) << 2;
        int t0 = (tile % 17) << 2;
        float4 acc0 = {0,0,0,0}, acc1 = {0,0,0,0}, acc2 = {0,0,0,0}, acc3 = {0,0,0,0};
        #pragma unroll 4
        for (int k = 0; k < HH; k += 4) {
            float4 a0 = *(const float4*)(A + (j0 + 0) * HH + k);
            float4 a1 = *(const float4*)(A + (j0 + 1) * HH + k);
            float4 a2 = *(const float4*)(A + (j0 + 2) * HH + k);
            float4 a3 = *(const float4*)(A + (j0 + 3) * HH + k);
            float4 b0 = *(const float4*)(sB + (k + 0) * SP + t0);
            float4 b1 = *(const float4*)(sB + (k + 1) * SP + t0);
            float4 b2 = *(const float4*)(sB + (k + 2) * SP + t0);
            float4 b3 = *(const float4*)(sB + (k + 3) * SP + t0);
            fma4(acc0, a0.x, b0); fma4(acc0, a0.y, b1); fma4(acc0, a0.z, b2); fma4(acc0, a0.w, b3);
            fma4(acc1, a1.x, b0); fma4(acc1, a1.y, b1); fma4(acc1, a1.z, b2); fma4(acc1, a1.w, b3);
            fma4(acc2, a2.x, b0); fma4(acc2, a2.y, b1); fma4(acc2, a2.z, b2); fma4(acc2, a2.w, b3);
            fma4(acc3, a3.x, b0); fma4(acc3, a3.y, b1); fma4(acc3, a3.z, b2); fma4(acc3, a3.w, b3);
        }
        *(float4*)(sC + (j0 + 0) * SP + t0) = acc0;
        *(float4*)(sC + (j0 + 1) * SP + t0) = acc1;
        *(float4*)(sC + (j0 + 2) * SP + t0) = acc2;
        *(float4*)(sC + (j0 + 3) * SP + t0) = acc3;
    }
}

// sKQ[s*SP + t] = sum_i sK[i*SP + s] * sQ[i*SP + t]   (sequential in-order over i)
__device__ __forceinline__ void gemm_kq(const float* __restrict__ sK,
                                        const float* __restrict__ sQ,
                                        float* __restrict__ sKQ) {
    for (int tile = threadIdx.x; tile < 34 * 17; tile += NT) {
        int s0 = (tile / 17) << 1;
        int t0 = (tile % 17) << 2;
        float4 acc0 = {0,0,0,0}, acc1 = {0,0,0,0};
        #pragma unroll 4
        for (int i = 0; i < HH; i++) {
            float a0 = sK[i * SP + s0 + 0];
            float a1 = sK[i * SP + s0 + 1];
            float4 b = *(const float4*)(sQ + i * SP + t0);
            fma4(acc0, a0, b);
            fma4(acc1, a1, b);
        }
        *(float4*)(sKQ + (s0 + 0) * SP + t0) = acc0;
        *(float4*)(sKQ + (s0 + 1) * SP + t0) = acc1;
    }
}

// row-wise softmax over t in [0,65), accurate expf + true division (match ref rounding)
__device__ __forceinline__ void softmax_rows(float* __restrict__ sKQ) {
    int warp = threadIdx.x >> 5, lane = threadIdx.x & 31;
    for (int s = warp; s < SS; s += NT / 32) {
        float* row = sKQ + s * SP;
        float v0 = row[lane], v1 = row[lane + 32], v2 = row[64];
        float m = fmaxf(fmaxf(v0, v1), v2);
        #pragma unroll
        for (int o = 16; o; o >>= 1) m = fmaxf(m, __shfl_xor_sync(0xffffffffu, m, o));
        float e0 = expf(v0 - m), e1 = expf(v1 - m), e2 = expf(v2 - m);
        float sum = e0 + e1;
        #pragma unroll
        for (int o = 16; o; o >>= 1) sum += __shfl_xor_sync(0xffffffffu, sum, o);
        float denom = sum + e2;
        row[lane] = e0 / denom;
        row[lane + 32] = e1 / denom;
        if (lane == 0) { row[64] = e2 / denom; row[65] = 0.f; row[66] = 0.f; row[67] = 0.f; }
    }
    if (threadIdx.x < 3 * SP) sKQ[SS * SP + threadIdx.x] = 0.f;  // zero rows 65..67
}

// sO[s*256 + i] = sum_t sKQ[s*SP + t] * sV[i*SP + t]   (in-order over t; pads are 0)
__device__ __forceinline__ void gemm_O(const float* __restrict__ sKQ,
                                       const float* __restrict__ sV,
                                       float* __restrict__ sO /* pre-offset by head */) {
    for (int tile = threadIdx.x; tile < 17 * 32; tile += NT) {
        int s0 = (tile / 32) << 2;
        int i0 = (tile % 32) << 2;
        float4 acc0 = {0,0,0,0}, acc1 = {0,0,0,0}, acc2 = {0,0,0,0}, acc3 = {0,0,0,0};
        #pragma unroll 4
        for (int t = 0; t < SP; t += 4) {
            float4 p0 = *(const float4*)(sKQ + (s0 + 0) * SP + t);
            float4 p1 = *(const float4*)(sKQ + (s0 + 1) * SP + t);
            float4 p2 = *(const float4*)(sKQ + (s0 + 2) * SP + t);
            float4 p3 = *(const float4*)(sKQ + (s0 + 3) * SP + t);
            float4 v0 = *(const float4*)(sV + (i0 + 0) * SP + t);
            float4 v1 = *(const float4*)(sV + (i0 + 1) * SP + t);
            float4 v2 = *(const float4*)(sV + (i0 + 2) * SP + t);
            float4 v3 = *(const float4*)(sV + (i0 + 3) * SP + t);
            acc0.x = dot4(p0, v0, acc0.x); acc0.y = dot4(p0, v1, acc0.y);
            acc0.z = dot4(p0, v2, acc0.z); acc0.w = dot4(p0, v3, acc0.w);
            acc1.x = dot4(p1, v0, acc1.x); acc1.y = dot4(p1, v1, acc1.y);
            acc1.z = dot4(p1, v2, acc1.z); acc1.w = dot4(p1, v3, acc1.w);
            acc2.x = dot4(p2, v0, acc2.x); acc2.y = dot4(p2, v1, acc2.y);
            acc2.z = dot4(p2, v2, acc2.z); acc2.w = dot4(p2, v3, acc2.w);
            acc3.x = dot4(p3, v0, acc3.x); acc3.y = dot4(p3, v1, acc3.y);
            acc3.z = dot4(p3, v2, acc3.z); acc3.w = dot4(p3, v3, acc3.w);
        }
        *(float4*)(sO + (s0 + 0) * 256 + i0) = acc0;
        *(float4*)(sO + (s0 + 1) * 256 + i0) = acc1;
        *(float4*)(sO + (s0 + 2) * 256 + i0) = acc2;
        *(float4*)(sO + (s0 + 3) * 256 + i0) = acc3;
    }
}

// sZ[s*HH + j] = sum_{i=0..255} sO[s*256 + i] * L[i*HH + j]  (ONE in-order 256 chain)
__device__ __forceinline__ void gemm_Z256(const float* __restrict__ sO,
                                          const float* __restrict__ L,
                                          float* __restrict__ sZ) {
    for (int tile = threadIdx.x; tile < 17 * 32; tile += NT) {
        int s0 = (tile / 32) << 2;
        int j0 = (tile % 32) << 2;
        float4 acc0 = {0,0,0,0}, acc1 = {0,0,0,0}, acc2 = {0,0,0,0}, acc3 = {0,0,0,0};
        #pragma unroll 4
        for (int i = 0; i < 256; i += 4) {
            float4 o0 = *(const float4*)(sO + (s0 + 0) * 256 + i);
            float4 o1 = *(const float4*)(sO + (s0 + 1) * 256 + i);
            float4 o2 = *(const float4*)(sO + (s0 + 2) * 256 + i);
            float4 o3 = *(const float4*)(sO + (s0 + 3) * 256 + i);
            float4 l0 = *(const float4*)(L + (i + 0) * HH + j0);
            float4 l1 = *(const float4*)(L + (i + 1) * HH + j0);
            float4 l2 = *(const float4*)(L + (i + 2) * HH + j0);
            float4 l3 = *(const float4*)(L + (i + 3) * HH + j0);
            fma4(acc0, o0.x, l0); fma4(acc0, o0.y, l1); fma4(acc0, o0.z, l2); fma4(acc0, o0.w, l3);
            fma4(acc1, o1.x, l0); fma4(acc1, o1.y, l1); fma4(acc1, o1.z, l2); fma4(acc1, o1.w, l3);
            fma4(acc2, o2.x, l0); fma4(acc2, o2.y, l1); fma4(acc2, o2.z, l2); fma4(acc2, o2.w, l3);
            fma4(acc3, o3.x, l0); fma4(acc3, o3.y, l1); fma4(acc3, o3.z, l2); fma4(acc3, o3.w, l3);
        }
        *(float4*)(sZ + (s0 + 0) * HH + j0) = acc0;
        *(float4*)(sZ + (s0 + 1) * HH + j0) = acc1;
        *(float4*)(sZ + (s0 + 2) * HH + j0) = acc2;
        *(float4*)(sZ + (s0 + 3) * HH + j0) = acc3;
    }
}

// smem layout (floats):
//  sY  @     0 : 8704  (128 x 68)
//  sK  @  8704 : 8704  (K; later Z [65 x 128])
//  sQ  @ 17408 : 8704  (Q; later V; later q2)
//  sO  @ 26112 : 17408 (68 x 256, both heads side by side)
//  sKQ @ 43520 : 4624  (68 x 68)
//  sEX @ 48144 : 1024
#define SMEM_FLOATS 49168

__global__ void __launch_bounds__(NT, 1) board_kernel(
    const float* __restrict__ inp, const float* __restrict__ emb,
    const float* __restrict__ wk11, const float* __restrict__ wq11, const float* __restrict__ wv11,
    const float* __restrict__ wk12, const float* __restrict__ wq12, const float* __restrict__ wv12,
    const float* __restrict__ L1,
    const float* __restrict__ wk21, const float* __restrict__ wq21, const float* __restrict__ wv21,
    const float* __restrict__ wk22, const float* __restrict__ wq22, const float* __restrict__ wv22,
    const float* __restrict__ L2, const float* __restrict__ L3, const float* __restrict__ L4,
    float* __restrict__ out) {
    extern __shared__ float sm[];
    float* sY  = sm;
    float* sK  = sm + 8704;     // K, then Z
    float* sQ  = sm + 17408;    // Q, then V, then q2
    float* sO  = sm + 26112;    // 68 x 256
    float* sKQ = sm + 43520;
    float* sEX = sm + 48144;

    float* sc   = sEX;          // 128 (layer-2 c = Wk2 @ y64)
    float* sw   = sEX + 128;    // 72 (softmax row)
    float* syw  = sEX + 200;    // 128
    float* satt = sEX + 328;    // 256
    float* sh2  = sEX + 584;    // 128
    float* sh3  = sEX + 712;    // 64

    const int b = blockIdx.x;
    const int tid = threadIdx.x;
    const float* x = inp + (size_t)b * 64;

    // Y[j][s] = emb[j][s] * x[s], x[64]=1; padding cols zero.
    for (int idx = tid; idx < HH * SP; idx += NT) {
        int j = idx / SP, s = idx - j * SP;
        float v = 0.f;
        if (s < 64)       v = emb[j * 65 + s] * x[s];
        else if (s == 64) v = emb[j * 65 + 64];
        sY[idx] = v;
    }
    __syncthreads();

    // ---- layer 1: two full attentions (explicit k, q — reference decomposition) ----
    #pragma unroll 1
    for (int a = 0; a < 2; a++) {
        const float* Wk = (a == 0) ? wk11 : wk12;
        const float* Wq = (a == 0) ? wq11 : wq12;
        const float* Wv = (a == 0) ? wv11 : wv12;
        gemm_gA(Wk, sY, sK);             // K = Wk @ Y
        gemm_gA(Wq, sY, sQ);             // Q = Wq @ Y
        __syncthreads();
        gemm_kq(sK, sQ, sKQ);            // KQ = K^T @ Q
        __syncthreads();
        softmax_rows(sKQ);               // softmax rows
        gemm_gA(Wv, sY, sQ);             // V = Wv @ Y (overwrites Q; kq reads done)
        __syncthreads();
        gemm_O(sKQ, sQ, sO + a * HH);    // O = SM @ V^T into columns [a*128, a*128+128)
        __syncthreads();
    }
    gemm_Z256(sO, L1, sK);               // Z = O @ L1, single 256-deep in-order chain
    __syncthreads();

    // tanh + transpose: Y2[j][s] = tanh(Z[s][j])
    for (int idx = tid; idx < HH * SP; idx += NT) {
        int j = idx / SP, s = idx - j * SP;
        sY[idx] = (s < SS) ? tanhf(sK[s * HH + j]) : 0.f;
    }
    __syncthreads();

    // ---- layer 2: only row s=64 of att needed, but logits via explicit q2 GEMM ----
    int lane = tid & 31;
    #pragma unroll 1
    for (int a2 = 0; a2 < 2; a2++) {
        const float* Wk = (a2 == 0) ? wk21 : wk22;
        const float* Wq = (a2 == 0) ? wq21 : wq22;
        const float* Wv = (a2 == 0) ? wv21 : wv22;
        gemm_gA(Wq, sY, sQ);                  // q2 = Wq @ Y2 (full, ref decomposition)
        if (tid < HH) {                       // c[i] = sum_j Wk[i][j] * y64[j]  (in-order)
            float acc = 0.f;
            #pragma unroll 8
            for (int j = 0; j < HH; j++)
                acc = fmaf(Wk[tid * HH + j], sY[j * SP + 64], acc);
            sc[tid] = acc;
        }
        __syncthreads();
        if (tid < SS) {                       // logits[t] = sum_i c[i] * q2[i][t]  (in-order)
            float acc = 0.f;
            #pragma unroll 8
            for (int i = 0; i < HH; i++)
                acc = fmaf(sc[i], sQ[i * SP + tid], acc);
            sw[tid] = acc;
        }
        __syncthreads();
        if (tid < 32) {                       // softmax (single row)
            float v0 = sw[lane], v1 = sw[lane + 32], v2 = sw[64];
            float m = fmaxf(fmaxf(v0, v1), v2);
            #pragma unroll
            for (int o = 16; o; o >>= 1) m = fmaxf(m, __shfl_xor_sync(0xffffffffu, m, o));
            float e0 = expf(v0 - m), e1 = expf(v1 - m), e2 = expf(v2 - m);
            float sum = e0 + e1;
            #pragma unroll
            for (int o = 16; o; o >>= 1) sum += __shfl_xor_sync(0xffffffffu, sum, o);
            float denom = sum + e2;
            sw[lane] = e0 / denom;
            sw[lane + 32] = e1 / denom;
            if (lane == 0) { sw[64] = e2 / denom; sw[65] = 0.f; sw[66] = 0.f; sw[67] = 0.f; }
        }
        __syncthreads();
        if (tid < HH) {                       // yw[j] = sum_t w[t] * Y2[j][t]
            float acc = 0.f;
            #pragma unroll
            for (int t = 0; t < SP; t += 4) {
                float4 y4 = *(const float4*)(sY + tid * SP + t);
                float4 w4 = *(const float4*)(sw + t);
                acc = dot4(y4, w4, acc);
            }
            syw[tid] = acc;
        }
        __syncthreads();
        if (tid < HH) {                       // att64[i] = sum_j Wv[i][j] * yw[j]
            float acc = 0.f;
            #pragma unroll 8
            for (int j = 0; j < HH; j += 4) {
                float4 w4 = *(const float4*)(Wv + tid * HH + j);
                float4 y4 = *(const float4*)(syw + j);
                acc = dot4(w4, y4, acc);
            }
            satt[a2 * HH + tid] = acc;
        }
        __syncthreads();
    }

    // head: h2 = tanh(cat(att) @ L2), h3 = tanh(h2 @ L3), score = h3 @ L4
    if (tid < HH) {
        float acc = 0.f;
        #pragma unroll 8
        for (int i = 0; i < 2 * HH; i++)
            acc = fmaf(satt[i], L2[i * HH + tid], acc);
        sh2[tid] = tanhf(acc);
    }
    __syncthreads();
    if (tid < 64) {
        float acc = 0.f;
        #pragma unroll 8
        for (int j = 0; j < HH; j++)
            acc = fmaf(sh2[j], L3[j * 64 + tid], acc);
        sh3[tid] = tanhf(acc);
    }
    __syncthreads();
    if (tid == 0) {
        float acc = 0.f;
        #pragma unroll
        for (int m = 0; m < 64; m++) acc = fmaf(sh3[m], L4[m], acc);
        out[b] = acc;
    }
}

extern "C" void kernel_launch(void* const* d_in, const int* in_sizes, int n_in,
                              void* d_out, int out_size) {
    const float* inputs = (const float*)d_in[0];
    const float* emb    = (const float*)d_in[1];
    const float* wk11   = (const float*)d_in[2];
    const float* wq11   = (const float*)d_in[3];
    const float* wv11   = (const float*)d_in[4];
    const float* wk12   = (const float*)d_in[5];
    const float* wq12   = (const float*)d_in[6];
    const float* wv12   = (const float*)d_in[7];
    const float* L1     = (const float*)d_in[8];
    const float* wk21   = (const float*)d_in[9];
    const float* wq21   = (const float*)d_in[10];
    const float* wv21   = (const float*)d_in[11];
    const float* wk22   = (const float*)d_in[12];
    const float* wq22   = (const float*)d_in[13];
    const float* wv22   = (const float*)d_in[14];
    const float* L2     = (const float*)d_in[15];
    const float* L3     = (const float*)d_in[16];
    const float* L4     = (const float*)d_in[17];
    (void)n_in; (void)in_sizes;

    int B = out_size;  // one score per board (8192)

    size_t smem = SMEM_FLOATS * sizeof(float);
    cudaFuncSetAttribute(board_kernel, cudaFuncAttributeMaxDynamicSharedMemorySize, (int)smem);

    board_kernel<<<B, NT, smem>>>(inputs, emb,
                                  wk11, wq11, wv11, wk12, wq12, wv12, L1,
                                  wk21, wq21, wv21, wk22, wq22, wv22, L2, L3, L4,
                                  (float*)d_out);
}